// round 1
// baseline (speedup 1.0000x reference)
#include <cuda_runtime.h>
#include <math.h>

#define NN0 100000
#define NN1 150000
#define NN2 50000
#define NNZ00 1600000
#define NNZ12 200000
#define DD 128

// ---------------- device scratch (static globals: no allocation) ----------------
__device__ float g_S0[(size_t)NN0 * DD];   // A00 @ relu(x0)
__device__ float g_S2[(size_t)NN2 * DD];   // B12 @ relu(x1)
__device__ int   g_rp0[NN0 + 1];
__device__ int   g_fill0[NN0];
__device__ int   g_pcol0[NNZ00];
__device__ float g_pval0[NNZ00];
__device__ int   g_rp2[NN2 + 1];
__device__ int   g_fill2[NN2];
__device__ int   g_pcol2[NNZ12];
__device__ float g_pval2[NNZ12];

// ---------------- kernels ----------------

__global__ void zero_counts_kernel() {
    int i = blockIdx.x * blockDim.x + threadIdx.x;
    if (i <= NN0) g_rp0[i] = 0;
    if (i <= NN2) g_rp2[i] = 0;
}

__global__ void relu_copy_kernel(const float* __restrict__ in,
                                 float* __restrict__ out, int n4) {
    int i = blockIdx.x * blockDim.x + threadIdx.x;
    if (i < n4) {
        float4 v = ((const float4*)in)[i];
        v.x = fmaxf(v.x, 0.f); v.y = fmaxf(v.y, 0.f);
        v.z = fmaxf(v.z, 0.f); v.w = fmaxf(v.w, 0.f);
        ((float4*)out)[i] = v;
    }
}

__global__ void hist_kernel(const int* __restrict__ rows, int nnz,
                            int* __restrict__ cnt) {
    int i = blockIdx.x * blockDim.x + threadIdx.x;
    if (i < nnz) atomicAdd(&cnt[rows[i]], 1);
}

// single-block exclusive scan over R counts (counts stored in row_ptr[0..R-1]);
// writes exclusive prefix into row_ptr[0..R-1] + row_ptr[R]=total, and copy into fill[].
__global__ void scan_kernel(int* __restrict__ row_ptr, int* __restrict__ fill, int R) {
    __shared__ int sums[1024];
    int tid = threadIdx.x;
    int chunk = (R + 1023) / 1024;
    int start = tid * chunk;
    int end   = start + chunk; if (end > R) end = R;
    int s = 0;
    for (int i = start; i < end; i++) s += row_ptr[i];
    sums[tid] = s;
    __syncthreads();
    // Hillis-Steele inclusive scan
    for (int off = 1; off < 1024; off <<= 1) {
        int v = (tid >= off) ? sums[tid - off] : 0;
        __syncthreads();
        sums[tid] += v;
        __syncthreads();
    }
    int run = (tid == 0) ? 0 : sums[tid - 1];
    for (int i = start; i < end; i++) {
        int c = row_ptr[i];
        row_ptr[i] = run;
        fill[i]    = run;
        run += c;
    }
    if (tid == 1023) row_ptr[R] = sums[1023];
}

__global__ void fill_kernel(const int* __restrict__ rows, const int* __restrict__ cols,
                            const float* __restrict__ vals, int nnz,
                            int* __restrict__ fill, int* __restrict__ pcol,
                            float* __restrict__ pval) {
    int i = blockIdx.x * blockDim.x + threadIdx.x;
    if (i < nnz) {
        int r = rows[i];
        int p = atomicAdd(&fill[r], 1);
        pcol[p] = cols[i];
        pval[p] = vals[i];
    }
}

// warp-per-row CSR SpMM with fused relu on the gathered dense rows.
// S[row, :] = sum_{e in row} val_e * relu(x[col_e, :])
__global__ void spmm_kernel(const float* __restrict__ x,
                            const int* __restrict__ rp,
                            const int* __restrict__ pcol,
                            const float* __restrict__ pval,
                            float* __restrict__ S, int nrows) {
    int warp = (blockIdx.x * blockDim.x + threadIdx.x) >> 5;
    int lane = threadIdx.x & 31;
    if (warp >= nrows) return;
    int s = rp[warp], e = rp[warp + 1];
    float4 acc = make_float4(0.f, 0.f, 0.f, 0.f);
    for (int i = s; i < e; i++) {
        int   c = pcol[i];
        float v = pval[i];
        float4 xv = *(const float4*)(x + (size_t)c * DD + lane * 4);
        xv.x = fmaxf(xv.x, 0.f); xv.y = fmaxf(xv.y, 0.f);
        xv.z = fmaxf(xv.z, 0.f); xv.w = fmaxf(xv.w, 0.f);
        acc.x += v * xv.x; acc.y += v * xv.y;
        acc.z += v * xv.z; acc.w += v * xv.w;
    }
    *(float4*)(S + (size_t)warp * DD + lane * 4) = acc;
}

// out[M,128] = relu(S[M,128] @ W[128,128]); W fully resident in smem.
// 64-row tile, 256 threads, 8x4 micro-tile (thread: rows rg*8..+7, cols cg*4..+3).
#define GEMM_SMEM ((DD * DD + 64 * DD) * 4)
__global__ __launch_bounds__(256, 2)
void gemm_relu_kernel(const float* __restrict__ S, const float* __restrict__ W,
                      float* __restrict__ out, int M) {
    extern __shared__ float smem[];
    float* sW = smem;            // 128 x 128
    float* sA = smem + DD * DD;  // 64 x 128
    int tid = threadIdx.x;

    const float4* Wg = (const float4*)W;
    float4* sW4 = (float4*)sW;
    #pragma unroll
    for (int i = tid; i < DD * DD / 4; i += 256) sW4[i] = Wg[i];

    int m0 = blockIdx.x * 64;
    float4* sA4 = (float4*)sA;
    for (int i = tid; i < 64 * DD / 4; i += 256) {
        int r  = i >> 5;            // 32 float4 per row
        int gr = m0 + r;
        float4 v = make_float4(0.f, 0.f, 0.f, 0.f);
        if (gr < M) v = ((const float4*)(S + (size_t)gr * DD))[i & 31];
        sA4[i] = v;
    }
    __syncthreads();

    int cg = tid & 31;     // col group: cols cg*4..cg*4+3
    int rg = tid >> 5;     // row group: rows rg*8..rg*8+7
    float4 acc[8];
    #pragma unroll
    for (int i = 0; i < 8; i++) acc[i] = make_float4(0.f, 0.f, 0.f, 0.f);

    const float4* W4 = (const float4*)sW;
    #pragma unroll 4
    for (int kk = 0; kk < DD; kk += 4) {
        float4 w0 = W4[(kk + 0) * 32 + cg];
        float4 w1 = W4[(kk + 1) * 32 + cg];
        float4 w2 = W4[(kk + 2) * 32 + cg];
        float4 w3 = W4[(kk + 3) * 32 + cg];
        #pragma unroll
        for (int i = 0; i < 8; i++) {
            const float4 a = *(const float4*)(sA + (rg * 8 + i) * DD + kk);
            acc[i].x += a.x * w0.x + a.y * w1.x + a.z * w2.x + a.w * w3.x;
            acc[i].y += a.x * w0.y + a.y * w1.y + a.z * w2.y + a.w * w3.y;
            acc[i].z += a.x * w0.z + a.y * w1.z + a.z * w2.z + a.w * w3.z;
            acc[i].w += a.x * w0.w + a.y * w1.w + a.z * w2.w + a.w * w3.w;
        }
    }

    #pragma unroll
    for (int i = 0; i < 8; i++) {
        int gr = m0 + rg * 8 + i;
        if (gr < M) {
            float4 r = acc[i];
            r.x = fmaxf(r.x, 0.f); r.y = fmaxf(r.y, 0.f);
            r.z = fmaxf(r.z, 0.f); r.w = fmaxf(r.w, 0.f);
            *(float4*)(out + (size_t)gr * DD + cg * 4) = r;
        }
    }
}

// ---------------- host launch ----------------
extern "C" void kernel_launch(void* const* d_in, const int* in_sizes, int n_in,
                              void* d_out, int out_size) {
    const float* x0  = (const float*)d_in[0];
    const float* x1  = (const float*)d_in[1];
    const int*   r00 = (const int*)  d_in[2];
    const int*   c00 = (const int*)  d_in[3];
    const float* v00 = (const float*)d_in[4];
    const int*   r12 = (const int*)  d_in[5];
    const int*   c12 = (const int*)  d_in[6];
    const float* v12 = (const float*)d_in[7];
    const float* W0  = (const float*)d_in[8];
    const float* W12 = (const float*)d_in[9];

    float* out    = (float*)d_out;
    float* out_y0 = out;
    float* out_x1 = out + (size_t)NN0 * DD;
    float* out_y2 = out + (size_t)(NN0 + NN1) * DD;

    void *pS0, *pS2, *prp0, *pf0, *ppc0, *ppv0, *prp2, *pf2, *ppc2, *ppv2;
    cudaGetSymbolAddress(&pS0,  g_S0);
    cudaGetSymbolAddress(&pS2,  g_S2);
    cudaGetSymbolAddress(&prp0, g_rp0);
    cudaGetSymbolAddress(&pf0,  g_fill0);
    cudaGetSymbolAddress(&ppc0, g_pcol0);
    cudaGetSymbolAddress(&ppv0, g_pval0);
    cudaGetSymbolAddress(&prp2, g_rp2);
    cudaGetSymbolAddress(&pf2,  g_fill2);
    cudaGetSymbolAddress(&ppc2, g_pcol2);
    cudaGetSymbolAddress(&ppv2, g_pval2);

    // 1) zero CSR count arrays
    zero_counts_kernel<<<(NN0 + 1 + 255) / 256, 256>>>();

    // 2) out_x1 = relu(x1)  (independent of CSR build)
    relu_copy_kernel<<<(NN1 * DD / 4 + 255) / 256, 256>>>(x1, out_x1, NN1 * DD / 4);

    // 3) CSR build for both edge sets
    hist_kernel<<<(NNZ00 + 255) / 256, 256>>>(r00, NNZ00, (int*)prp0);
    hist_kernel<<<(NNZ12 + 255) / 256, 256>>>(r12, NNZ12, (int*)prp2);
    scan_kernel<<<1, 1024>>>((int*)prp0, (int*)pf0, NN0);
    scan_kernel<<<1, 1024>>>((int*)prp2, (int*)pf2, NN2);
    fill_kernel<<<(NNZ00 + 255) / 256, 256>>>(r00, c00, v00, NNZ00,
                                              (int*)pf0, (int*)ppc0, (float*)ppv0);
    fill_kernel<<<(NNZ12 + 255) / 256, 256>>>(r12, c12, v12, NNZ12,
                                              (int*)pf2, (int*)ppc2, (float*)ppv2);

    // 4) SpMM first (associativity: A @ (X W) == (A @ X) W), relu fused on gather
    spmm_kernel<<<(NN0 * 32 + 255) / 256, 256>>>(x0, (const int*)prp0, (const int*)ppc0,
                                                 (const float*)ppv0, (float*)pS0, NN0);
    spmm_kernel<<<(NN2 * 32 + 255) / 256, 256>>>(x1, (const int*)prp2, (const int*)ppc2,
                                                 (const float*)ppv2, (float*)pS2, NN2);

    // 5) small dense GEMMs with fused relu epilogue, straight into d_out
    cudaFuncSetAttribute(gemm_relu_kernel,
                         cudaFuncAttributeMaxDynamicSharedMemorySize, GEMM_SMEM);
    gemm_relu_kernel<<<(NN0 + 63) / 64, 256, GEMM_SMEM>>>((const float*)pS0, W0,  out_y0, NN0);
    gemm_relu_kernel<<<(NN2 + 63) / 64, 256, GEMM_SMEM>>>((const float*)pS2, W12, out_y2, NN2);
}

// round 2
// speedup vs baseline: 1.0155x; 1.0155x over previous
#include <cuda_runtime.h>
#include <math.h>
#include <stdint.h>

#define NN0 100000
#define NN1 150000
#define NN2 50000
#define NNZ00 1600000
#define NNZ12 200000
#define DD 128

// ---------------- device scratch (static globals: no allocation) ----------------
__device__ float g_S0[(size_t)NN0 * DD];   // A00 @ relu(x0)
__device__ float g_S2[(size_t)NN2 * DD];   // B12 @ relu(x1)
__device__ int   g_rp0[NN0 + 1];
__device__ int   g_fill0[NN0];
__device__ int   g_pcol0[NNZ00];
__device__ float g_pval0[NNZ00];
__device__ int   g_rp2[NN2 + 1];
__device__ int   g_fill2[NN2];
__device__ int   g_pcol2[NNZ12];
__device__ float g_pval2[NNZ12];

// ---------------- CSR build ----------------

__global__ void zero_counts_kernel() {
    int i = blockIdx.x * blockDim.x + threadIdx.x;
    if (i <= NN0) g_rp0[i] = 0;
    if (i <= NN2) g_rp2[i] = 0;
}

__global__ void relu_copy_kernel(const float* __restrict__ in,
                                 float* __restrict__ out, int n4) {
    int i = blockIdx.x * blockDim.x + threadIdx.x;
    if (i < n4) {
        float4 v = ((const float4*)in)[i];
        v.x = fmaxf(v.x, 0.f); v.y = fmaxf(v.y, 0.f);
        v.z = fmaxf(v.z, 0.f); v.w = fmaxf(v.w, 0.f);
        ((float4*)out)[i] = v;
    }
}

__global__ void hist_kernel(const int* __restrict__ rows, int nnz,
                            int* __restrict__ cnt) {
    int i = blockIdx.x * blockDim.x + threadIdx.x;
    if (i < nnz) atomicAdd(&cnt[rows[i]], 1);
}

// single-block exclusive scan over R counts
__global__ void scan_kernel(int* __restrict__ row_ptr, int* __restrict__ fill, int R) {
    __shared__ int sums[1024];
    int tid = threadIdx.x;
    int chunk = (R + 1023) / 1024;
    int start = tid * chunk;
    int end   = start + chunk; if (end > R) end = R;
    int s = 0;
    for (int i = start; i < end; i++) s += row_ptr[i];
    sums[tid] = s;
    __syncthreads();
    for (int off = 1; off < 1024; off <<= 1) {
        int v = (tid >= off) ? sums[tid - off] : 0;
        __syncthreads();
        sums[tid] += v;
        __syncthreads();
    }
    int run = (tid == 0) ? 0 : sums[tid - 1];
    for (int i = start; i < end; i++) {
        int c = row_ptr[i];
        row_ptr[i] = run;
        fill[i]    = run;
        run += c;
    }
    if (tid == 1023) row_ptr[R] = sums[1023];
}

__global__ void fill_kernel(const int* __restrict__ rows, const int* __restrict__ cols,
                            const float* __restrict__ vals, int nnz,
                            int* __restrict__ fill, int* __restrict__ pcol,
                            float* __restrict__ pval) {
    int i = blockIdx.x * blockDim.x + threadIdx.x;
    if (i < nnz) {
        int r = rows[i];
        int p = atomicAdd(&fill[r], 1);
        pcol[p] = cols[i];
        pval[p] = vals[i];
    }
}

// ---------------- SpMM: warp-per-row, relu fused on gather, 2-edge unroll ----------------
__global__ void spmm_kernel(const float* __restrict__ x,
                            const int* __restrict__ rp,
                            const int* __restrict__ pcol,
                            const float* __restrict__ pval,
                            float* __restrict__ S, int nrows) {
    int warp = (blockIdx.x * blockDim.x + threadIdx.x) >> 5;
    int lane = threadIdx.x & 31;
    if (warp >= nrows) return;
    int s = rp[warp], e = rp[warp + 1];
    float4 acc = make_float4(0.f, 0.f, 0.f, 0.f);
    int i = s;
    for (; i + 2 <= e; i += 2) {
        int   c0 = pcol[i],     c1 = pcol[i + 1];
        float v0 = pval[i],     v1 = pval[i + 1];
        float4 xa = *(const float4*)(x + (size_t)c0 * DD + lane * 4);
        float4 xb = *(const float4*)(x + (size_t)c1 * DD + lane * 4);
        acc.x += v0 * fmaxf(xa.x, 0.f) + v1 * fmaxf(xb.x, 0.f);
        acc.y += v0 * fmaxf(xa.y, 0.f) + v1 * fmaxf(xb.y, 0.f);
        acc.z += v0 * fmaxf(xa.z, 0.f) + v1 * fmaxf(xb.z, 0.f);
        acc.w += v0 * fmaxf(xa.w, 0.f) + v1 * fmaxf(xb.w, 0.f);
    }
    if (i < e) {
        int   c0 = pcol[i];
        float v0 = pval[i];
        float4 xa = *(const float4*)(x + (size_t)c0 * DD + lane * 4);
        acc.x += v0 * fmaxf(xa.x, 0.f);
        acc.y += v0 * fmaxf(xa.y, 0.f);
        acc.z += v0 * fmaxf(xa.z, 0.f);
        acc.w += v0 * fmaxf(xa.w, 0.f);
    }
    *(float4*)(S + (size_t)warp * DD + lane * 4) = acc;
}

// ---------------- GEMM: 3xTF32 mma.sync, fused relu epilogue ----------------
// out[M,128] = relu(S[M,128] @ W[128,128])
// Block: 64 rows x 128 cols, 256 threads = 8 warps (2 m-groups x 4 n-groups).
// Warp: 32 rows x 32 cols = 2 m16-tiles x 4 n8-tiles, k=8 per mma, 16 k-steps.
#define PADA 132   // bank = (4g + i) mod 32 -> bijective over warp (conflict-free)
#define PADW 136   // bank = (8i + g) mod 32 -> bijective over warp (conflict-free)
#define GSMEM ((128 * PADW + 64 * PADA) * 4)

__device__ __forceinline__ void split_tf32(float a, uint32_t& hi, uint32_t& lo) {
    uint32_t h = __float_as_uint(a) & 0xffffe000u;   // truncate to tf32-representable
    hi = h;
    float r = a - __uint_as_float(h);                // exact residual
    asm("cvt.rna.tf32.f32 %0, %1;" : "=r"(lo) : "f"(r));
}

__device__ __forceinline__ void mma_tf32(float* d, const uint32_t* a, const uint32_t* b) {
    asm volatile(
        "mma.sync.aligned.m16n8k8.row.col.f32.tf32.tf32.f32 "
        "{%0,%1,%2,%3}, {%4,%5,%6,%7}, {%8,%9}, {%0,%1,%2,%3};\n"
        : "+f"(d[0]), "+f"(d[1]), "+f"(d[2]), "+f"(d[3])
        : "r"(a[0]), "r"(a[1]), "r"(a[2]), "r"(a[3]), "r"(b[0]), "r"(b[1]));
}

__global__ __launch_bounds__(256, 2)
void gemm_tf32_relu_kernel(const float* __restrict__ S, const float* __restrict__ W,
                           float* __restrict__ out, int M) {
    extern __shared__ float smem[];
    float* sW = smem;              // [128][PADW], row-major (k rows, n cols)
    float* sA = smem + 128 * PADW; // [64][PADA],  row-major (m rows, k cols)
    int tid = threadIdx.x;
    int m0 = blockIdx.x * 64;

    // stage W (128x128)
    for (int idx = tid; idx < 128 * 32; idx += 256) {
        int r = idx >> 5, c = (idx & 31) << 2;
        float4 v = *(const float4*)(W + r * DD + c);
        float* p = sW + r * PADW + c;
        p[0] = v.x; p[1] = v.y; p[2] = v.z; p[3] = v.w;
    }
    // stage A (64x128, zero-fill tail rows)
    for (int idx = tid; idx < 64 * 32; idx += 256) {
        int r = idx >> 5, c = (idx & 31) << 2;
        int gr = m0 + r;
        float4 v = make_float4(0.f, 0.f, 0.f, 0.f);
        if (gr < M) v = *(const float4*)(S + (size_t)gr * DD + c);
        float* p = sA + r * PADA + c;
        p[0] = v.x; p[1] = v.y; p[2] = v.z; p[3] = v.w;
    }
    __syncthreads();

    int lane = tid & 31, wid = tid >> 5;
    int g = lane >> 2, i = lane & 3;     // groupID, threadID-in-group
    int mg = wid & 1, ng = wid >> 1;     // 2 x 4 warp grid

    float acc[2][4][4];
    #pragma unroll
    for (int mt = 0; mt < 2; mt++)
        #pragma unroll
        for (int nt = 0; nt < 4; nt++)
            #pragma unroll
            for (int q = 0; q < 4; q++) acc[mt][nt][q] = 0.f;

    #pragma unroll
    for (int kk = 0; kk < 16; kk++) {
        int k0 = kk * 8;
        uint32_t ah[2][4], al[2][4], bh[4][2], bl[4][2];
        #pragma unroll
        for (int mt = 0; mt < 2; mt++) {
            int rb = (mg * 32 + mt * 16 + g) * PADA + k0 + i;
            float a0 = sA[rb];
            float a1 = sA[rb + 8 * PADA];
            float a2 = sA[rb + 4];
            float a3 = sA[rb + 8 * PADA + 4];
            split_tf32(a0, ah[mt][0], al[mt][0]);
            split_tf32(a1, ah[mt][1], al[mt][1]);
            split_tf32(a2, ah[mt][2], al[mt][2]);
            split_tf32(a3, ah[mt][3], al[mt][3]);
        }
        #pragma unroll
        for (int nt = 0; nt < 4; nt++) {
            int cb = (k0 + i) * PADW + ng * 32 + nt * 8 + g;
            float b0 = sW[cb];
            float b1 = sW[cb + 4 * PADW];
            split_tf32(b0, bh[nt][0], bl[nt][0]);
            split_tf32(b1, bh[nt][1], bl[nt][1]);
        }
        #pragma unroll
        for (int mt = 0; mt < 2; mt++)
            #pragma unroll
            for (int nt = 0; nt < 4; nt++) {
                mma_tf32(acc[mt][nt], ah[mt], bl[nt]);  // small terms first
                mma_tf32(acc[mt][nt], al[mt], bh[nt]);
                mma_tf32(acc[mt][nt], ah[mt], bh[nt]);  // big term last
            }
    }

    // epilogue: relu + store (float2 per c-pair, coalesced)
    #pragma unroll
    for (int mt = 0; mt < 2; mt++) {
        int r0 = m0 + mg * 32 + mt * 16 + g;
        #pragma unroll
        for (int nt = 0; nt < 4; nt++) {
            int c = ng * 32 + nt * 8 + i * 2;
            if (r0 < M) {
                float2 v = make_float2(fmaxf(acc[mt][nt][0], 0.f),
                                       fmaxf(acc[mt][nt][1], 0.f));
                *(float2*)(out + (size_t)r0 * DD + c) = v;
            }
            if (r0 + 8 < M) {
                float2 v = make_float2(fmaxf(acc[mt][nt][2], 0.f),
                                       fmaxf(acc[mt][nt][3], 0.f));
                *(float2*)(out + (size_t)(r0 + 8) * DD + c) = v;
            }
        }
    }
}

// ---------------- host launch ----------------
extern "C" void kernel_launch(void* const* d_in, const int* in_sizes, int n_in,
                              void* d_out, int out_size) {
    const float* x0  = (const float*)d_in[0];
    const float* x1  = (const float*)d_in[1];
    const int*   r00 = (const int*)  d_in[2];
    const int*   c00 = (const int*)  d_in[3];
    const float* v00 = (const float*)d_in[4];
    const int*   r12 = (const int*)  d_in[5];
    const int*   c12 = (const int*)  d_in[6];
    const float* v12 = (const float*)d_in[7];
    const float* W0  = (const float*)d_in[8];
    const float* W12 = (const float*)d_in[9];

    float* out    = (float*)d_out;
    float* out_y0 = out;
    float* out_x1 = out + (size_t)NN0 * DD;
    float* out_y2 = out + (size_t)(NN0 + NN1) * DD;

    void *pS0, *pS2, *prp0, *pf0, *ppc0, *ppv0, *prp2, *pf2, *ppc2, *ppv2;
    cudaGetSymbolAddress(&pS0,  g_S0);
    cudaGetSymbolAddress(&pS2,  g_S2);
    cudaGetSymbolAddress(&prp0, g_rp0);
    cudaGetSymbolAddress(&pf0,  g_fill0);
    cudaGetSymbolAddress(&ppc0, g_pcol0);
    cudaGetSymbolAddress(&ppv0, g_pval0);
    cudaGetSymbolAddress(&prp2, g_rp2);
    cudaGetSymbolAddress(&pf2,  g_fill2);
    cudaGetSymbolAddress(&ppc2, g_pcol2);
    cudaGetSymbolAddress(&ppv2, g_pval2);

    // 1) zero CSR count arrays
    zero_counts_kernel<<<(NN0 + 1 + 255) / 256, 256>>>();

    // 2) out_x1 = relu(x1)
    relu_copy_kernel<<<(NN1 * DD / 4 + 255) / 256, 256>>>(x1, out_x1, NN1 * DD / 4);

    // 3) CSR build
    hist_kernel<<<(NNZ00 + 255) / 256, 256>>>(r00, NNZ00, (int*)prp0);
    hist_kernel<<<(NNZ12 + 255) / 256, 256>>>(r12, NNZ12, (int*)prp2);
    scan_kernel<<<1, 1024>>>((int*)prp0, (int*)pf0, NN0);
    scan_kernel<<<1, 1024>>>((int*)prp2, (int*)pf2, NN2);
    fill_kernel<<<(NNZ00 + 255) / 256, 256>>>(r00, c00, v00, NNZ00,
                                              (int*)pf0, (int*)ppc0, (float*)ppv0);
    fill_kernel<<<(NNZ12 + 255) / 256, 256>>>(r12, c12, v12, NNZ12,
                                              (int*)pf2, (int*)ppc2, (float*)ppv2);

    // 4) SpMM first (associativity: A @ (X W) == (A @ X) W), relu fused on gather
    spmm_kernel<<<(NN0 * 32 + 255) / 256, 256>>>(x0, (const int*)prp0, (const int*)ppc0,
                                                 (const float*)ppv0, (float*)pS0, NN0);
    spmm_kernel<<<(NN2 * 32 + 255) / 256, 256>>>(x1, (const int*)prp2, (const int*)ppc2,
                                                 (const float*)ppv2, (float*)pS2, NN2);

    // 5) tensor-core GEMMs (3xTF32) with fused relu, straight into d_out
    cudaFuncSetAttribute(gemm_tf32_relu_kernel,
                         cudaFuncAttributeMaxDynamicSharedMemorySize, GSMEM);
    gemm_tf32_relu_kernel<<<(NN0 + 63) / 64, 256, GSMEM>>>((const float*)pS0, W0,  out_y0, NN0);
    gemm_tf32_relu_kernel<<<(NN2 + 63) / 64, 256, GSMEM>>>((const float*)pS2, W12, out_y2, NN2);
}

// round 4
// speedup vs baseline: 1.8179x; 1.7901x over previous
#include <cuda_runtime.h>
#include <math.h>
#include <stdint.h>

#define NN0 100000
#define NN1 150000
#define NN2 50000
#define NNZ00 1600000
#define NNZ12 200000
#define DD 128

#define NB0 98              // ceil(NN0/1024)
#define NB2 49              // ceil(NN2/1024)

// ---------------- device scratch (static globals: no allocation) ----------------
__device__ float g_S0[(size_t)NN0 * DD];
__device__ float g_S2[(size_t)NN2 * DD];
__device__ __align__(16) int g_rp0[NN0 + 1];
__device__ __align__(16) int g_fill0[NN0];     // counts, then fill cursors
__device__ __align__(16) int g_rp2[NN2 + 1];
__device__ __align__(16) int g_fill2[NN2];
__device__ int   g_part0[128];
__device__ int   g_part2[128];
__device__ int   g_pcol0[NNZ00];
__device__ float g_pval0[NNZ00];
__device__ int   g_pcol2[NNZ12];
__device__ float g_pval2[NNZ12];

// ---------------- small/build kernels ----------------

__global__ void zero_counts_kernel() {
    int i = blockIdx.x * blockDim.x + threadIdx.x;
    if (i < NN0) g_fill0[i] = 0;
    if (i < NN2) g_fill2[i] = 0;
}

__global__ void relu_copy_kernel(const float* __restrict__ in,
                                 float* __restrict__ out, int n4) {
    int i = blockIdx.x * blockDim.x + threadIdx.x;
    if (i < n4) {
        float4 v = ((const float4*)in)[i];
        v.x = fmaxf(v.x, 0.f); v.y = fmaxf(v.y, 0.f);
        v.z = fmaxf(v.z, 0.f); v.w = fmaxf(v.w, 0.f);
        ((float4*)out)[i] = v;
    }
}

__global__ void hist2_kernel(const int* __restrict__ r00, const int* __restrict__ r12) {
    int i = blockIdx.x * blockDim.x + threadIdx.x;
    if (i < NNZ00) {
        atomicAdd(&g_fill0[r00[i]], 1);
    } else {
        int j = i - NNZ00;
        if (j < NNZ12) atomicAdd(&g_fill2[r12[j]], 1);
    }
}

// ---- two-level scan: stage 1 (per-1024-chunk exclusive scan, coalesced) ----
__device__ __forceinline__ void scan_chunk(const int* __restrict__ cnt,
                                           int* __restrict__ outx,
                                           int* __restrict__ partials,
                                           int b, int R) {
    __shared__ int wsum[8];
    int tid = threadIdx.x;                 // 256 threads, 4 elems each
    int base = b * 1024 + tid * 4;
    int c0 = 0, c1 = 0, c2 = 0, c3 = 0;
    if (base + 3 < R) {
        int4 v = *(const int4*)(cnt + base);
        c0 = v.x; c1 = v.y; c2 = v.z; c3 = v.w;
    } else {
        if (base + 0 < R) c0 = cnt[base + 0];
        if (base + 1 < R) c1 = cnt[base + 1];
        if (base + 2 < R) c2 = cnt[base + 2];
    }
    int t = c0 + c1 + c2 + c3;
    int lane = tid & 31, w = tid >> 5;
    int inc = t;
    #pragma unroll
    for (int off = 1; off < 32; off <<= 1) {
        int v = __shfl_up_sync(0xffffffffu, inc, off);
        if (lane >= off) inc += v;
    }
    if (lane == 31) wsum[w] = inc;
    __syncthreads();
    if (tid == 0) {
        int run = 0;
        #pragma unroll
        for (int i = 0; i < 8; i++) { int v = wsum[i]; wsum[i] = run; run += v; }
        partials[b] = run;
    }
    __syncthreads();
    int ex = wsum[w] + inc - t;
    if (base + 3 < R) {
        int4 o;
        o.x = ex; o.y = ex + c0; o.z = ex + c0 + c1; o.w = ex + c0 + c1 + c2;
        *(int4*)(outx + base) = o;
    } else {
        if (base + 0 < R) outx[base + 0] = ex;
        if (base + 1 < R) outx[base + 1] = ex + c0;
        if (base + 2 < R) outx[base + 2] = ex + c0 + c1;
    }
}

__global__ void scan_block_kernel() {
    int b = blockIdx.x;
    if (b < NB0) scan_chunk(g_fill0, g_rp0, g_part0, b, NN0);
    else         scan_chunk(g_fill2, g_rp2, g_part2, b - NB0, NN2);
}

// ---- stage 2: scan the partials (tiny, one block) ----
__global__ void scan_partials_kernel() {
    __shared__ int sh[128];
    int tid = threadIdx.x;   // 128 threads
    // phase 0: g_part0 (NB0 entries)
    int orig = (tid < NB0) ? g_part0[tid] : 0;
    sh[tid] = orig;
    __syncthreads();
    #pragma unroll
    for (int off = 1; off < 128; off <<= 1) {
        int v = (tid >= off) ? sh[tid - off] : 0;
        __syncthreads();
        sh[tid] += v;
        __syncthreads();
    }
    if (tid < NB0) g_part0[tid] = sh[tid] - orig;   // exclusive
    if (tid == 127) g_rp0[NN0] = sh[127];
    __syncthreads();
    // phase 1: g_part2 (NB2 entries)
    orig = (tid < NB2) ? g_part2[tid] : 0;
    sh[tid] = orig;
    __syncthreads();
    #pragma unroll
    for (int off = 1; off < 128; off <<= 1) {
        int v = (tid >= off) ? sh[tid - off] : 0;
        __syncthreads();
        sh[tid] += v;
        __syncthreads();
    }
    if (tid < NB2) g_part2[tid] = sh[tid] - orig;
    if (tid == 127) g_rp2[NN2] = sh[127];
}

// ---- stage 3: add chunk offsets, copy into fill cursors ----
__global__ void add_offsets_kernel() {
    int b = blockIdx.x, tid = threadIdx.x;   // 1024 threads
    if (b < NB0) {
        int idx = b * 1024 + tid;
        if (idx < NN0) {
            int v = g_rp0[idx] + g_part0[b];
            g_rp0[idx] = v; g_fill0[idx] = v;
        }
    } else {
        int bb = b - NB0;
        int idx = bb * 1024 + tid;
        if (idx < NN2) {
            int v = g_rp2[idx] + g_part2[bb];
            g_rp2[idx] = v; g_fill2[idx] = v;
        }
    }
}

__global__ void fill2_kernel(const int* __restrict__ r00, const int* __restrict__ c00,
                             const float* __restrict__ v00,
                             const int* __restrict__ r12, const int* __restrict__ c12,
                             const float* __restrict__ v12) {
    int i = blockIdx.x * blockDim.x + threadIdx.x;
    if (i < NNZ00) {
        int p = atomicAdd(&g_fill0[r00[i]], 1);
        g_pcol0[p] = c00[i];
        g_pval0[p] = v00[i];
    } else {
        int j = i - NNZ00;
        if (j < NNZ12) {
            int p = atomicAdd(&g_fill2[r12[j]], 1);
            g_pcol2[p] = c12[j];
            g_pval2[p] = v12[j];
        }
    }
}

// ---------------- SpMM: warp-per-row, relu fused, both matrices in one grid ----------------
__device__ __forceinline__ void spmm_row(const float* __restrict__ x,
                                         const int* __restrict__ rp,
                                         const int* __restrict__ pcol,
                                         const float* __restrict__ pval,
                                         float* __restrict__ S, int row, int lane) {
    int s = rp[row], e = rp[row + 1];
    float4 acc = make_float4(0.f, 0.f, 0.f, 0.f);
    int i = s;
    for (; i + 2 <= e; i += 2) {
        int   c0 = pcol[i],     c1 = pcol[i + 1];
        float v0 = pval[i],     v1 = pval[i + 1];
        float4 xa = *(const float4*)(x + (size_t)c0 * DD + lane * 4);
        float4 xb = *(const float4*)(x + (size_t)c1 * DD + lane * 4);
        acc.x += v0 * fmaxf(xa.x, 0.f) + v1 * fmaxf(xb.x, 0.f);
        acc.y += v0 * fmaxf(xa.y, 0.f) + v1 * fmaxf(xb.y, 0.f);
        acc.z += v0 * fmaxf(xa.z, 0.f) + v1 * fmaxf(xb.z, 0.f);
        acc.w += v0 * fmaxf(xa.w, 0.f) + v1 * fmaxf(xb.w, 0.f);
    }
    if (i < e) {
        int   c0 = pcol[i];
        float v0 = pval[i];
        float4 xa = *(const float4*)(x + (size_t)c0 * DD + lane * 4);
        acc.x += v0 * fmaxf(xa.x, 0.f);
        acc.y += v0 * fmaxf(xa.y, 0.f);
        acc.z += v0 * fmaxf(xa.z, 0.f);
        acc.w += v0 * fmaxf(xa.w, 0.f);
    }
    *(float4*)(S + (size_t)row * DD + lane * 4) = acc;
}

__global__ void spmm2_kernel(const float* __restrict__ x0, const float* __restrict__ x1) {
    int warp = (blockIdx.x * blockDim.x + threadIdx.x) >> 5;
    int lane = threadIdx.x & 31;
    if (warp < NN0)            spmm_row(x0, g_rp0, g_pcol0, g_pval0, g_S0, warp, lane);
    else if (warp < NN0 + NN2) spmm_row(x1, g_rp2, g_pcol2, g_pval2, g_S2, warp - NN0, lane);
}

// ---------------- GEMM: 3xTF32 mma.sync, fused relu, both GEMMs in one grid ----------------
#define PADA 132
#define PADW 136
#define GSMEM ((128 * PADW + 64 * PADA) * 4)
#define NBLK0 ((NN0 + 63) / 64)
#define NBLK2 ((NN2 + 63) / 64)

__device__ __forceinline__ void split_tf32(float a, uint32_t& hi, uint32_t& lo) {
    uint32_t h = __float_as_uint(a) & 0xffffe000u;
    hi = h;
    float r = a - __uint_as_float(h);
    asm("cvt.rna.tf32.f32 %0, %1;" : "=r"(lo) : "f"(r));
}

__device__ __forceinline__ void mma_tf32(float* d, const uint32_t* a, const uint32_t* b) {
    asm volatile(
        "mma.sync.aligned.m16n8k8.row.col.f32.tf32.tf32.f32 "
        "{%0,%1,%2,%3}, {%4,%5,%6,%7}, {%8,%9}, {%0,%1,%2,%3};\n"
        : "+f"(d[0]), "+f"(d[1]), "+f"(d[2]), "+f"(d[3])
        : "r"(a[0]), "r"(a[1]), "r"(a[2]), "r"(a[3]), "r"(b[0]), "r"(b[1]));
}

__global__ __launch_bounds__(256, 2)
void gemm2_tf32_relu_kernel(const float* __restrict__ W0, const float* __restrict__ W12,
                            float* __restrict__ out_y0, float* __restrict__ out_y2) {
    const float* S; const float* W; float* out; int M, bid;
    if (blockIdx.x < NBLK0) { S = g_S0; W = W0;  out = out_y0; M = NN0; bid = blockIdx.x; }
    else                    { S = g_S2; W = W12; out = out_y2; M = NN2; bid = blockIdx.x - NBLK0; }

    extern __shared__ float smem[];
    float* sW = smem;              // [128][PADW]
    float* sA = smem + 128 * PADW; // [64][PADA]
    int tid = threadIdx.x;
    int m0 = bid * 64;

    for (int idx = tid; idx < 128 * 32; idx += 256) {
        int r = idx >> 5, c = (idx & 31) << 2;
        float4 v = *(const float4*)(W + r * DD + c);
        float* p = sW + r * PADW + c;
        p[0] = v.x; p[1] = v.y; p[2] = v.z; p[3] = v.w;
    }
    for (int idx = tid; idx < 64 * 32; idx += 256) {
        int r = idx >> 5, c = (idx & 31) << 2;
        int gr = m0 + r;
        float4 v = make_float4(0.f, 0.f, 0.f, 0.f);
        if (gr < M) v = *(const float4*)(S + (size_t)gr * DD + c);
        float* p = sA + r * PADA + c;
        p[0] = v.x; p[1] = v.y; p[2] = v.z; p[3] = v.w;
    }
    __syncthreads();

    int lane = tid & 31, wid = tid >> 5;
    int g = lane >> 2, i = lane & 3;
    int mg = wid & 1, ng = wid >> 1;

    float acc[2][4][4];
    #pragma unroll
    for (int mt = 0; mt < 2; mt++)
        #pragma unroll
        for (int nt = 0; nt < 4; nt++)
            #pragma unroll
            for (int q = 0; q < 4; q++) acc[mt][nt][q] = 0.f;

    #pragma unroll
    for (int kk = 0; kk < 16; kk++) {
        int k0 = kk * 8;
        uint32_t ah[2][4], al[2][4], bh[4][2], bl[4][2];
        #pragma unroll
        for (int mt = 0; mt < 2; mt++) {
            int rb = (mg * 32 + mt * 16 + g) * PADA + k0 + i;
            split_tf32(sA[rb],                ah[mt][0], al[mt][0]);
            split_tf32(sA[rb + 8 * PADA],     ah[mt][1], al[mt][1]);
            split_tf32(sA[rb + 4],            ah[mt][2], al[mt][2]);
            split_tf32(sA[rb + 8 * PADA + 4], ah[mt][3], al[mt][3]);
        }
        #pragma unroll
        for (int nt = 0; nt < 4; nt++) {
            int cb = (k0 + i) * PADW + ng * 32 + nt * 8 + g;
            split_tf32(sW[cb],            bh[nt][0], bl[nt][0]);
            split_tf32(sW[cb + 4 * PADW], bh[nt][1], bl[nt][1]);
        }
        #pragma unroll
        for (int mt = 0; mt < 2; mt++)
            #pragma unroll
            for (int nt = 0; nt < 4; nt++) {
                mma_tf32(acc[mt][nt], ah[mt], bl[nt]);
                mma_tf32(acc[mt][nt], al[mt], bh[nt]);
                mma_tf32(acc[mt][nt], ah[mt], bh[nt]);
            }
    }

    #pragma unroll
    for (int mt = 0; mt < 2; mt++) {
        int r0 = m0 + mg * 32 + mt * 16 + g;
        #pragma unroll
        for (int nt = 0; nt < 4; nt++) {
            int c = ng * 32 + nt * 8 + i * 2;
            if (r0 < M) {
                float2 v = make_float2(fmaxf(acc[mt][nt][0], 0.f),
                                       fmaxf(acc[mt][nt][1], 0.f));
                *(float2*)(out + (size_t)r0 * DD + c) = v;
            }
            if (r0 + 8 < M) {
                float2 v = make_float2(fmaxf(acc[mt][nt][2], 0.f),
                                       fmaxf(acc[mt][nt][3], 0.f));
                *(float2*)(out + (size_t)(r0 + 8) * DD + c) = v;
            }
        }
    }
}

// ---------------- host launch ----------------
extern "C" void kernel_launch(void* const* d_in, const int* in_sizes, int n_in,
                              void* d_out, int out_size) {
    const float* x0  = (const float*)d_in[0];
    const float* x1  = (const float*)d_in[1];
    const int*   r00 = (const int*)  d_in[2];
    const int*   c00 = (const int*)  d_in[3];
    const float* v00 = (const float*)d_in[4];
    const int*   r12 = (const int*)  d_in[5];
    const int*   c12 = (const int*)  d_in[6];
    const float* v12 = (const float*)d_in[7];
    const float* W0  = (const float*)d_in[8];
    const float* W12 = (const float*)d_in[9];

    float* out    = (float*)d_out;
    float* out_y0 = out;
    float* out_x1 = out + (size_t)NN0 * DD;
    float* out_y2 = out + (size_t)(NN0 + NN1) * DD;

    // 1) zero counts
    zero_counts_kernel<<<(NN0 + 255) / 256, 256>>>();
    // 2) out_x1 = relu(x1)
    relu_copy_kernel<<<(NN1 * DD / 4 + 255) / 256, 256>>>(x1, out_x1, NN1 * DD / 4);
    // 3) histogram both edge sets
    hist2_kernel<<<(NNZ00 + NNZ12 + 255) / 256, 256>>>(r00, r12);
    // 4) two-level scan (both matrices share the grids)
    scan_block_kernel<<<NB0 + NB2, 256>>>();
    scan_partials_kernel<<<1, 128>>>();
    add_offsets_kernel<<<NB0 + NB2, 1024>>>();
    // 5) CSR fill
    fill2_kernel<<<(NNZ00 + NNZ12 + 255) / 256, 256>>>(r00, c00, v00, r12, c12, v12);
    // 6) SpMM (associativity: A @ (X W) == (A @ X) W), relu fused on gather
    spmm2_kernel<<<((NN0 + NN2) * 32 + 255) / 256, 256>>>(x0, x1);
    // 7) tensor-core GEMMs (3xTF32) with fused relu, straight into d_out
    cudaFuncSetAttribute(gemm2_tf32_relu_kernel,
                         cudaFuncAttributeMaxDynamicSharedMemorySize, GSMEM);
    gemm2_tf32_relu_kernel<<<NBLK0 + NBLK2, 256, GSMEM>>>(W0, W12, out_y0, out_y2);
}

// round 5
// speedup vs baseline: 1.8986x; 1.0444x over previous
#include <cuda_runtime.h>
#include <math.h>
#include <stdint.h>

#define NN0 100000
#define NN1 150000
#define NN2 50000
#define NNZ00 1600000
#define NNZ12 200000
#define DD 128

#define NB0 98              // ceil(NN0/1024)
#define NB2 49              // ceil(NN2/1024)
#define NBT (NB0 + NB2)     // 147 <= 148 SMs: all blocks co-resident

// ---------------- device scratch (static globals: zero-initialized) ----------------
__device__ float g_S0[(size_t)NN0 * DD];
__device__ float g_S2[(size_t)NN2 * DD];
__device__ __align__(16) int g_rp0[NN0 + 4];
__device__ __align__(16) int g_fill0[NN0];     // counts -> fill cursors (re-zeroed by tail)
__device__ __align__(16) int g_rp2[NN2 + 4];
__device__ __align__(16) int g_fill2[NN2];
__device__ int  g_flagA[NBT];                  // lookback flags (re-zeroed by tail)
__device__ int2 g_e0[NNZ00];                   // packed {col, val_bits}
__device__ int2 g_e2[NNZ12];

// ---------------- histogram (both edge sets, one grid) ----------------
__global__ void hist2_kernel(const int* __restrict__ r00, const int* __restrict__ r12) {
    int i = blockIdx.x * blockDim.x + threadIdx.x;
    if (i < NNZ00) {
        atomicAdd(&g_fill0[r00[i]], 1);
    } else {
        int j = i - NNZ00;
        if (j < NNZ12) atomicAdd(&g_fill2[r12[j]], 1);
    }
}

// ---------------- single-kernel scan: block-local scan + decoupled lookback ----------------
__global__ void scan_fused_kernel() {
    __shared__ int wsum[8];
    __shared__ int s_off;
    int b = blockIdx.x;
    const int* cnt; int* rp; int* fill; int R; int base0; int lastcb;
    if (b < NB0) { cnt = g_fill0; rp = g_rp0; fill = g_fill0; R = NN0; base0 = 0;   lastcb = NB0 - 1; }
    else         { cnt = g_fill2; rp = g_rp2; fill = g_fill2; R = NN2; base0 = NB0; lastcb = NB2 - 1; }
    int cb  = b - base0;
    int tid = threadIdx.x;                 // 256 threads, 4 elems each
    int base = cb * 1024 + tid * 4;

    int c0 = 0, c1 = 0, c2 = 0, c3 = 0;
    if (base + 3 < R) {
        int4 v = *(const int4*)(cnt + base);
        c0 = v.x; c1 = v.y; c2 = v.z; c3 = v.w;
    } else {
        if (base + 0 < R) c0 = cnt[base + 0];
        if (base + 1 < R) c1 = cnt[base + 1];
        if (base + 2 < R) c2 = cnt[base + 2];
    }
    int t = c0 + c1 + c2 + c3;
    int lane = tid & 31, w = tid >> 5;
    int inc = t;
    #pragma unroll
    for (int off = 1; off < 32; off <<= 1) {
        int v = __shfl_up_sync(0xffffffffu, inc, off);
        if (lane >= off) inc += v;
    }
    if (lane == 31) wsum[w] = inc;
    if (tid == 0) s_off = 0;
    __syncthreads();

    int agg = 0;
    if (tid == 0) {
        int run = 0;
        #pragma unroll
        for (int i = 0; i < 8; i++) { int v = wsum[i]; wsum[i] = run; run += v; }
        agg = run;
        atomicExch(&g_flagA[b], run + 1);       // publish aggregate (nonzero marker)
    }
    __syncthreads();

    // lookback: sum published aggregates of all predecessor chunks of this matrix
    int local = 0;
    for (int j = base0 + tid; j < b; j += 256) {
        int v;
        while ((v = *(volatile int*)&g_flagA[j]) == 0) __nanosleep(20);
        local += v - 1;
    }
    if (local) atomicAdd(&s_off, local);
    __syncthreads();
    int off = s_off;

    int ex = off + wsum[w] + inc - t;          // global exclusive prefix for c0
    if (base + 3 < R) {
        int4 o; o.x = ex; o.y = ex + c0; o.z = ex + c0 + c1; o.w = ex + c0 + c1 + c2;
        *(int4*)(rp + base)   = o;
        *(int4*)(fill + base) = o;
    } else {
        if (base + 0 < R) { rp[base + 0] = ex;               fill[base + 0] = ex; }
        if (base + 1 < R) { rp[base + 1] = ex + c0;          fill[base + 1] = ex + c0; }
        if (base + 2 < R) { rp[base + 2] = ex + c0 + c1;     fill[base + 2] = ex + c0 + c1; }
    }
    if (tid == 0 && cb == lastcb) rp[R] = off + agg;
}

// ---------------- CSR fill: packed 8B edge stores ----------------
__global__ void fill2_kernel(const int* __restrict__ r00, const int* __restrict__ c00,
                             const float* __restrict__ v00,
                             const int* __restrict__ r12, const int* __restrict__ c12,
                             const float* __restrict__ v12) {
    int i = blockIdx.x * blockDim.x + threadIdx.x;
    if (i < NNZ00) {
        int p = atomicAdd(&g_fill0[r00[i]], 1);
        g_e0[p] = make_int2(c00[i], __float_as_int(v00[i]));
    } else {
        int j = i - NNZ00;
        if (j < NNZ12) {
            int p = atomicAdd(&g_fill2[r12[j]], 1);
            g_e2[p] = make_int2(c12[j], __float_as_int(v12[j]));
        }
    }
}

// ---------------- SpMM: warp-per-row, relu fused, 4-edge unroll (MLP=4) ----------------
__device__ __forceinline__ void spmm_row(const float* __restrict__ x,
                                         const int* __restrict__ rp,
                                         const int2* __restrict__ ed,
                                         float* __restrict__ S, int row, int lane) {
    int s = rp[row], e = rp[row + 1];
    float4 acc = make_float4(0.f, 0.f, 0.f, 0.f);
    int i = s;
    for (; i + 4 <= e; i += 4) {
        int2 e0 = ed[i], e1 = ed[i + 1], e2 = ed[i + 2], e3 = ed[i + 3];
        float4 xa = *(const float4*)(x + (size_t)e0.x * DD + lane * 4);
        float4 xb = *(const float4*)(x + (size_t)e1.x * DD + lane * 4);
        float4 xc = *(const float4*)(x + (size_t)e2.x * DD + lane * 4);
        float4 xd = *(const float4*)(x + (size_t)e3.x * DD + lane * 4);
        float v0 = __int_as_float(e0.y), v1 = __int_as_float(e1.y);
        float v2 = __int_as_float(e2.y), v3 = __int_as_float(e3.y);
        acc.x += v0 * fmaxf(xa.x, 0.f) + v1 * fmaxf(xb.x, 0.f)
               + v2 * fmaxf(xc.x, 0.f) + v3 * fmaxf(xd.x, 0.f);
        acc.y += v0 * fmaxf(xa.y, 0.f) + v1 * fmaxf(xb.y, 0.f)
               + v2 * fmaxf(xc.y, 0.f) + v3 * fmaxf(xd.y, 0.f);
        acc.z += v0 * fmaxf(xa.z, 0.f) + v1 * fmaxf(xb.z, 0.f)
               + v2 * fmaxf(xc.z, 0.f) + v3 * fmaxf(xd.z, 0.f);
        acc.w += v0 * fmaxf(xa.w, 0.f) + v1 * fmaxf(xb.w, 0.f)
               + v2 * fmaxf(xc.w, 0.f) + v3 * fmaxf(xd.w, 0.f);
    }
    for (; i < e; i++) {
        int2 e0 = ed[i];
        float v0 = __int_as_float(e0.y);
        float4 xa = *(const float4*)(x + (size_t)e0.x * DD + lane * 4);
        acc.x += v0 * fmaxf(xa.x, 0.f);
        acc.y += v0 * fmaxf(xa.y, 0.f);
        acc.z += v0 * fmaxf(xa.z, 0.f);
        acc.w += v0 * fmaxf(xa.w, 0.f);
    }
    *(float4*)(S + (size_t)row * DD + lane * 4) = acc;
}

__global__ void spmm2_kernel(const float* __restrict__ x0, const float* __restrict__ x1) {
    int warp = (blockIdx.x * blockDim.x + threadIdx.x) >> 5;
    int lane = threadIdx.x & 31;
    if (warp < NN0)            spmm_row(x0, g_rp0, g_e0, g_S0, warp, lane);
    else if (warp < NN0 + NN2) spmm_row(x1, g_rp2, g_e2, g_S2, warp - NN0, lane);
}

// ---------------- GEMM: 3xTF32 mma.sync, fused relu, both GEMMs in one grid ----------------
#define PADA 132
#define PADW 136
#define GSMEM ((128 * PADW + 64 * PADA) * 4)
#define NBLK0 ((NN0 + 63) / 64)
#define NBLK2 ((NN2 + 63) / 64)

__device__ __forceinline__ void split_tf32(float a, uint32_t& hi, uint32_t& lo) {
    uint32_t h = __float_as_uint(a) & 0xffffe000u;
    hi = h;
    float r = a - __uint_as_float(h);
    asm("cvt.rna.tf32.f32 %0, %1;" : "=r"(lo) : "f"(r));
}

__device__ __forceinline__ void mma_tf32(float* d, const uint32_t* a, const uint32_t* b) {
    asm volatile(
        "mma.sync.aligned.m16n8k8.row.col.f32.tf32.tf32.f32 "
        "{%0,%1,%2,%3}, {%4,%5,%6,%7}, {%8,%9}, {%0,%1,%2,%3};\n"
        : "+f"(d[0]), "+f"(d[1]), "+f"(d[2]), "+f"(d[3])
        : "r"(a[0]), "r"(a[1]), "r"(a[2]), "r"(a[3]), "r"(b[0]), "r"(b[1]));
}

__global__ __launch_bounds__(256, 2)
void gemm2_tf32_relu_kernel(const float* __restrict__ W0, const float* __restrict__ W12,
                            float* __restrict__ out_y0, float* __restrict__ out_y2) {
    const float* S; const float* W; float* out; int M, bid;
    if (blockIdx.x < NBLK0) { S = g_S0; W = W0;  out = out_y0; M = NN0; bid = blockIdx.x; }
    else                    { S = g_S2; W = W12; out = out_y2; M = NN2; bid = blockIdx.x - NBLK0; }

    extern __shared__ float smem[];
    float* sW = smem;              // [128][PADW]
    float* sA = smem + 128 * PADW; // [64][PADA]
    int tid = threadIdx.x;
    int m0 = bid * 64;

    for (int idx = tid; idx < 128 * 32; idx += 256) {
        int r = idx >> 5, c = (idx & 31) << 2;
        float4 v = *(const float4*)(W + r * DD + c);
        float* p = sW + r * PADW + c;
        p[0] = v.x; p[1] = v.y; p[2] = v.z; p[3] = v.w;
    }
    for (int idx = tid; idx < 64 * 32; idx += 256) {
        int r = idx >> 5, c = (idx & 31) << 2;
        int gr = m0 + r;
        float4 v = make_float4(0.f, 0.f, 0.f, 0.f);
        if (gr < M) v = *(const float4*)(S + (size_t)gr * DD + c);
        float* p = sA + r * PADA + c;
        p[0] = v.x; p[1] = v.y; p[2] = v.z; p[3] = v.w;
    }
    __syncthreads();

    int lane = tid & 31, wid = tid >> 5;
    int g = lane >> 2, i = lane & 3;
    int mg = wid & 1, ng = wid >> 1;

    float acc[2][4][4];
    #pragma unroll
    for (int mt = 0; mt < 2; mt++)
        #pragma unroll
        for (int nt = 0; nt < 4; nt++)
            #pragma unroll
            for (int q = 0; q < 4; q++) acc[mt][nt][q] = 0.f;

    #pragma unroll
    for (int kk = 0; kk < 16; kk++) {
        int k0 = kk * 8;
        uint32_t ah[2][4], al[2][4], bh[4][2], bl[4][2];
        #pragma unroll
        for (int mt = 0; mt < 2; mt++) {
            int rb = (mg * 32 + mt * 16 + g) * PADA + k0 + i;
            split_tf32(sA[rb],                ah[mt][0], al[mt][0]);
            split_tf32(sA[rb + 8 * PADA],     ah[mt][1], al[mt][1]);
            split_tf32(sA[rb + 4],            ah[mt][2], al[mt][2]);
            split_tf32(sA[rb + 8 * PADA + 4], ah[mt][3], al[mt][3]);
        }
        #pragma unroll
        for (int nt = 0; nt < 4; nt++) {
            int cb = (k0 + i) * PADW + ng * 32 + nt * 8 + g;
            split_tf32(sW[cb],            bh[nt][0], bl[nt][0]);
            split_tf32(sW[cb + 4 * PADW], bh[nt][1], bl[nt][1]);
        }
        #pragma unroll
        for (int mt = 0; mt < 2; mt++)
            #pragma unroll
            for (int nt = 0; nt < 4; nt++) {
                mma_tf32(acc[mt][nt], ah[mt], bl[nt]);
                mma_tf32(acc[mt][nt], al[mt], bh[nt]);
                mma_tf32(acc[mt][nt], ah[mt], bh[nt]);
            }
    }

    #pragma unroll
    for (int mt = 0; mt < 2; mt++) {
        int r0 = m0 + mg * 32 + mt * 16 + g;
        #pragma unroll
        for (int nt = 0; nt < 4; nt++) {
            int c = ng * 32 + nt * 8 + i * 2;
            if (r0 < M) {
                float2 v = make_float2(fmaxf(acc[mt][nt][0], 0.f),
                                       fmaxf(acc[mt][nt][1], 0.f));
                *(float2*)(out + (size_t)r0 * DD + c) = v;
            }
            if (r0 + 8 < M) {
                float2 v = make_float2(fmaxf(acc[mt][nt][2], 0.f),
                                       fmaxf(acc[mt][nt][3], 0.f));
                *(float2*)(out + (size_t)(r0 + 8) * DD + c) = v;
            }
        }
    }
}

// ---------------- tail: re-zero scratch for next replay + relu(x1) output ----------------
#define ZTOT (NN0 + NN2 + NBT)
#define RELU4 (NN1 * DD / 4)
__global__ void tail_kernel(const float* __restrict__ x1, float* __restrict__ out_x1) {
    int i = blockIdx.x * blockDim.x + threadIdx.x;
    if (i < NN0) {
        g_fill0[i] = 0;
    } else if (i < NN0 + NN2) {
        g_fill2[i - NN0] = 0;
    } else if (i < ZTOT) {
        g_flagA[i - NN0 - NN2] = 0;
    } else {
        int j = i - ZTOT;
        if (j < RELU4) {
            float4 v = ((const float4*)x1)[j];
            v.x = fmaxf(v.x, 0.f); v.y = fmaxf(v.y, 0.f);
            v.z = fmaxf(v.z, 0.f); v.w = fmaxf(v.w, 0.f);
            ((float4*)out_x1)[j] = v;
        }
    }
}

// ---------------- host launch ----------------
extern "C" void kernel_launch(void* const* d_in, const int* in_sizes, int n_in,
                              void* d_out, int out_size) {
    const float* x0  = (const float*)d_in[0];
    const float* x1  = (const float*)d_in[1];
    const int*   r00 = (const int*)  d_in[2];
    const int*   c00 = (const int*)  d_in[3];
    const float* v00 = (const float*)d_in[4];
    const int*   r12 = (const int*)  d_in[5];
    const int*   c12 = (const int*)  d_in[6];
    const float* v12 = (const float*)d_in[7];
    const float* W0  = (const float*)d_in[8];
    const float* W12 = (const float*)d_in[9];

    float* out    = (float*)d_out;
    float* out_y0 = out;
    float* out_x1 = out + (size_t)NN0 * DD;
    float* out_y2 = out + (size_t)(NN0 + NN1) * DD;

    // counts/flags are zero on entry: zero-initialized globals on first call,
    // re-zeroed by tail_kernel on every subsequent replay.
    hist2_kernel<<<(NNZ00 + NNZ12 + 255) / 256, 256>>>(r00, r12);          // #1
    scan_fused_kernel<<<NBT, 256>>>();                                     // #2
    fill2_kernel<<<(NNZ00 + NNZ12 + 255) / 256, 256>>>(r00, c00, v00,
                                                       r12, c12, v12);    // #3
    spmm2_kernel<<<((NN0 + NN2) * 32 + 255) / 256, 256>>>(x0, x1);         // #4 (profiled)
    cudaFuncSetAttribute(gemm2_tf32_relu_kernel,
                         cudaFuncAttributeMaxDynamicSharedMemorySize, GSMEM);
    gemm2_tf32_relu_kernel<<<NBLK0 + NBLK2, 256, GSMEM>>>(W0, W12,
                                                          out_y0, out_y2); // #5
    tail_kernel<<<(ZTOT + RELU4 + 255) / 256, 256>>>(x1, out_x1);          // #6
}

// round 6
// speedup vs baseline: 1.9926x; 1.0495x over previous
#include <cuda_runtime.h>
#include <cuda_fp16.h>
#include <math.h>
#include <stdint.h>

#define NN0 100000
#define NN1 150000
#define NN2 50000
#define NNZ00 1600000
#define NNZ12 200000
#define DD 128

#define NB0 98              // ceil(NN0/1024)
#define NB2 49              // ceil(NN2/1024)
#define NBT (NB0 + NB2)     // 147 <= 148 SMs: all blocks co-resident at occ 1
#define NAT (NBT * 1024)    // total threads in fused front kernel

// ---------------- device scratch (zero-initialized; tail restores zeros) ----------------
__device__ uint2 g_h0[(size_t)NN0 * 32];       // relu(x0) as fp16, 4 halves per uint2
__device__ uint2 g_h1[(size_t)NN1 * 32];       // relu(x1) as fp16
__device__ uint2 g_S0h[(size_t)NN0 * 32];      // S0 = A00 @ relu(x0), fp16
__device__ uint2 g_S2h[(size_t)NN2 * 32];      // S2 = B12 @ relu(x1), fp16
__device__ __align__(16) int g_rp0[NN0 + 4];
__device__ __align__(16) int g_fill0[NN0];     // counts -> cursors (re-zeroed by tail)
__device__ __align__(16) int g_rp2[NN2 + 4];
__device__ __align__(16) int g_fill2[NN2];
__device__ int  g_flagA[NBT];
__device__ int  g_bar1, g_bar2;                // grid barrier counters (re-zeroed by tail)
__device__ int2 g_e0[NNZ00];                   // packed {col, val_bits}
__device__ int2 g_e2[NNZ12];

// ---------------- fused front: hist + fp16 conversions + out_x1 + scan ----------------
__device__ __forceinline__ void grid_barrier(int* ctr) {
    __syncthreads();
    if (threadIdx.x == 0) {
        atomicAdd(ctr, 1);
        while (*(volatile int*)ctr < NBT) __nanosleep(40);
    }
    __syncthreads();
}

__global__ __launch_bounds__(1024, 1)
void front_kernel(const float* __restrict__ x0, const float* __restrict__ x1,
                  const int* __restrict__ r00, const int* __restrict__ r12,
                  float* __restrict__ out_x1) {
    int tid  = threadIdx.x;
    int gtid = blockIdx.x * 1024 + tid;

    // --- phase 1a: histogram both edge sets ---
    for (int i = gtid; i < NNZ00; i += NAT) atomicAdd(&g_fill0[r00[i]], 1);
    for (int i = gtid; i < NNZ12; i += NAT) atomicAdd(&g_fill2[r12[i]], 1);

    // --- phase 1b: relu + fp16 conversion of x0, x1 (+ fp32 relu(x1) to d_out) ---
    for (int i = gtid; i < NN0 * 32; i += NAT) {
        float4 v = ((const float4*)x0)[i];
        half2 p0 = __floats2half2_rn(fmaxf(v.x, 0.f), fmaxf(v.y, 0.f));
        half2 p1 = __floats2half2_rn(fmaxf(v.z, 0.f), fmaxf(v.w, 0.f));
        g_h0[i] = make_uint2(*(uint32_t*)&p0, *(uint32_t*)&p1);
    }
    for (int i = gtid; i < NN1 * 32; i += NAT) {
        float4 v = ((const float4*)x1)[i];
        v.x = fmaxf(v.x, 0.f); v.y = fmaxf(v.y, 0.f);
        v.z = fmaxf(v.z, 0.f); v.w = fmaxf(v.w, 0.f);
        ((float4*)out_x1)[i] = v;
        half2 p0 = __floats2half2_rn(v.x, v.y);
        half2 p1 = __floats2half2_rn(v.z, v.w);
        g_h1[i] = make_uint2(*(uint32_t*)&p0, *(uint32_t*)&p1);
    }

    grid_barrier(&g_bar1);

    // --- phase 2: per-chunk scan (1024 elems, 1 per thread) ---
    __shared__ int wsum[32];
    __shared__ int s_off;
    int b = blockIdx.x;
    int* cntfill; int* rp; int R; int base0; int lastcb;
    if (b < NB0) { cntfill = g_fill0; rp = g_rp0; R = NN0; base0 = 0;   lastcb = NB0 - 1; }
    else         { cntfill = g_fill2; rp = g_rp2; R = NN2; base0 = NB0; lastcb = NB2 - 1; }
    int cb  = b - base0;
    int idx = cb * 1024 + tid;
    int c = (idx < R) ? cntfill[idx] : 0;

    int lane = tid & 31, w = tid >> 5;
    int inc = c;
    #pragma unroll
    for (int off = 1; off < 32; off <<= 1) {
        int v = __shfl_up_sync(0xffffffffu, inc, off);
        if (lane >= off) inc += v;
    }
    if (lane == 31) wsum[w] = inc;
    if (tid == 0) s_off = 0;
    __syncthreads();
    if (w == 0) {
        int v = wsum[lane];
        int winc = v;
        #pragma unroll
        for (int off = 1; off < 32; off <<= 1) {
            int u = __shfl_up_sync(0xffffffffu, winc, off);
            if (lane >= off) winc += u;
        }
        wsum[lane] = winc - v;                  // exclusive
        if (lane == 31) g_flagA[b] = winc;      // block aggregate
    }

    grid_barrier(&g_bar2);

    int local = 0;
    for (int j = base0 + tid; j < b; j += 1024) local += g_flagA[j];
    if (local) atomicAdd(&s_off, local);
    __syncthreads();
    int off = s_off;

    if (idx < R) {
        int v = off + wsum[w] + inc - c;        // global exclusive prefix
        rp[idx]      = v;
        cntfill[idx] = v;                       // fill cursor
    }
    if (tid == 1023 && cb == lastcb) rp[R] = off + wsum[31] + inc;  // total of last chunk + off
}

// ---------------- CSR fill: packed 8B edge stores ----------------
__global__ void fill2_kernel(const int* __restrict__ r00, const int* __restrict__ c00,
                             const float* __restrict__ v00,
                             const int* __restrict__ r12, const int* __restrict__ c12,
                             const float* __restrict__ v12) {
    int i = blockIdx.x * blockDim.x + threadIdx.x;
    if (i < NNZ00) {
        int p = atomicAdd(&g_fill0[r00[i]], 1);
        g_e0[p] = make_int2(c00[i], __float_as_int(v00[i]));
    } else {
        int j = i - NNZ00;
        if (j < NNZ12) {
            int p = atomicAdd(&g_fill2[r12[j]], 1);
            g_e2[p] = make_int2(c12[j], __float_as_int(v12[j]));
        }
    }
}

// ---------------- SpMM: warp-per-row, fp16 gather (256B/row), fp32 accum, fp16 store ----------------
__device__ __forceinline__ float4 h4f(uint2 q) {
    float2 f0 = __half22float2(*(half2*)&q.x);
    float2 f1 = __half22float2(*(half2*)&q.y);
    return make_float4(f0.x, f0.y, f1.x, f1.y);
}

__device__ __forceinline__ void spmm_row(const uint2* __restrict__ xh,
                                         const int* __restrict__ rp,
                                         const int2* __restrict__ ed,
                                         uint2* __restrict__ S, int row, int lane) {
    int s = rp[row], e = rp[row + 1];
    float4 acc = make_float4(0.f, 0.f, 0.f, 0.f);
    int i = s;
    for (; i + 4 <= e; i += 4) {
        int2 e0 = ed[i], e1 = ed[i + 1], e2 = ed[i + 2], e3 = ed[i + 3];
        float4 xa = h4f(xh[(size_t)e0.x * 32 + lane]);
        float4 xb = h4f(xh[(size_t)e1.x * 32 + lane]);
        float4 xc = h4f(xh[(size_t)e2.x * 32 + lane]);
        float4 xd = h4f(xh[(size_t)e3.x * 32 + lane]);
        float v0 = __int_as_float(e0.y), v1 = __int_as_float(e1.y);
        float v2 = __int_as_float(e2.y), v3 = __int_as_float(e3.y);
        acc.x += v0 * xa.x + v1 * xb.x + v2 * xc.x + v3 * xd.x;
        acc.y += v0 * xa.y + v1 * xb.y + v2 * xc.y + v3 * xd.y;
        acc.z += v0 * xa.z + v1 * xb.z + v2 * xc.z + v3 * xd.z;
        acc.w += v0 * xa.w + v1 * xb.w + v2 * xc.w + v3 * xd.w;
    }
    for (; i < e; i++) {
        int2 e0 = ed[i];
        float v0 = __int_as_float(e0.y);
        float4 xa = h4f(xh[(size_t)e0.x * 32 + lane]);
        acc.x += v0 * xa.x; acc.y += v0 * xa.y;
        acc.z += v0 * xa.z; acc.w += v0 * xa.w;
    }
    half2 p0 = __floats2half2_rn(acc.x, acc.y);
    half2 p1 = __floats2half2_rn(acc.z, acc.w);
    S[(size_t)row * 32 + lane] = make_uint2(*(uint32_t*)&p0, *(uint32_t*)&p1);
}

__global__ void spmm2_kernel() {
    int warp = (blockIdx.x * blockDim.x + threadIdx.x) >> 5;
    int lane = threadIdx.x & 31;
    if (warp < NN0)            spmm_row(g_h0, g_rp0, g_e0, g_S0h, warp, lane);
    else if (warp < NN0 + NN2) spmm_row(g_h1, g_rp2, g_e2, g_S2h, warp - NN0, lane);
}

// ---------------- GEMM: A fp16 (tf32-exact, no split) x W split -> 2 mmas, relu fused ----------------
#define PADA 132
#define PADW 136
#define GSMEM ((128 * PADW + 64 * PADA) * 4)
#define NBLK0 ((NN0 + 63) / 64)
#define NBLK2 ((NN2 + 63) / 64)

__device__ __forceinline__ void split_tf32(float a, uint32_t& hi, uint32_t& lo) {
    uint32_t h = __float_as_uint(a) & 0xffffe000u;
    hi = h;
    float r = a - __uint_as_float(h);
    asm("cvt.rna.tf32.f32 %0, %1;" : "=r"(lo) : "f"(r));
}

__device__ __forceinline__ void mma_tf32(float* d, const uint32_t* a, const uint32_t* b) {
    asm volatile(
        "mma.sync.aligned.m16n8k8.row.col.f32.tf32.tf32.f32 "
        "{%0,%1,%2,%3}, {%4,%5,%6,%7}, {%8,%9}, {%0,%1,%2,%3};\n"
        : "+f"(d[0]), "+f"(d[1]), "+f"(d[2]), "+f"(d[3])
        : "r"(a[0]), "r"(a[1]), "r"(a[2]), "r"(a[3]), "r"(b[0]), "r"(b[1]));
}

__global__ __launch_bounds__(256, 2)
void gemm2_tf32_relu_kernel(const float* __restrict__ W0, const float* __restrict__ W12,
                            float* __restrict__ out_y0, float* __restrict__ out_y2) {
    const uint2* Sh; const float* W; float* out; int M, bid;
    if (blockIdx.x < NBLK0) { Sh = g_S0h; W = W0;  out = out_y0; M = NN0; bid = blockIdx.x; }
    else                    { Sh = g_S2h; W = W12; out = out_y2; M = NN2; bid = blockIdx.x - NBLK0; }

    extern __shared__ float smem[];
    float* sW = smem;              // [128][PADW]
    float* sA = smem + 128 * PADW; // [64][PADA]
    int tid = threadIdx.x;
    int m0 = bid * 64;

    for (int idx = tid; idx < 128 * 32; idx += 256) {
        int r = idx >> 5, c = (idx & 31) << 2;
        float4 v = *(const float4*)(W + r * DD + c);
        float* p = sW + r * PADW + c;
        p[0] = v.x; p[1] = v.y; p[2] = v.z; p[3] = v.w;
    }
    for (int idx = tid; idx < 64 * 32; idx += 256) {
        int r = idx >> 5, q = idx & 31;
        int gr = m0 + r;
        float4 v = make_float4(0.f, 0.f, 0.f, 0.f);
        if (gr < M) v = h4f(Sh[(size_t)gr * 32 + q]);
        float* p = sA + r * PADA + q * 4;
        p[0] = v.x; p[1] = v.y; p[2] = v.z; p[3] = v.w;
    }
    __syncthreads();

    int lane = tid & 31, wid = tid >> 5;
    int g = lane >> 2, i = lane & 3;
    int mg = wid & 1, ng = wid >> 1;

    float acc[2][4][4];
    #pragma unroll
    for (int mt = 0; mt < 2; mt++)
        #pragma unroll
        for (int nt = 0; nt < 4; nt++)
            #pragma unroll
            for (int q = 0; q < 4; q++) acc[mt][nt][q] = 0.f;

    #pragma unroll
    for (int kk = 0; kk < 16; kk++) {
        int k0 = kk * 8;
        uint32_t ah[2][4], bh[4][2], bl[4][2];
        #pragma unroll
        for (int mt = 0; mt < 2; mt++) {
            int rb = (mg * 32 + mt * 16 + g) * PADA + k0 + i;
            // fp16-sourced values are tf32-exact: use fp32 bits directly
            ah[mt][0] = __float_as_uint(sA[rb]);
            ah[mt][1] = __float_as_uint(sA[rb + 8 * PADA]);
            ah[mt][2] = __float_as_uint(sA[rb + 4]);
            ah[mt][3] = __float_as_uint(sA[rb + 8 * PADA + 4]);
        }
        #pragma unroll
        for (int nt = 0; nt < 4; nt++) {
            int cb = (k0 + i) * PADW + ng * 32 + nt * 8 + g;
            split_tf32(sW[cb],            bh[nt][0], bl[nt][0]);
            split_tf32(sW[cb + 4 * PADW], bh[nt][1], bl[nt][1]);
        }
        #pragma unroll
        for (int mt = 0; mt < 2; mt++)
            #pragma unroll
            for (int nt = 0; nt < 4; nt++) {
                mma_tf32(acc[mt][nt], ah[mt], bl[nt]);   // small term first
                mma_tf32(acc[mt][nt], ah[mt], bh[nt]);
            }
    }

    #pragma unroll
    for (int mt = 0; mt < 2; mt++) {
        int r0 = m0 + mg * 32 + mt * 16 + g;
        #pragma unroll
        for (int nt = 0; nt < 4; nt++) {
            int c = ng * 32 + nt * 8 + i * 2;
            if (r0 < M) {
                float2 v = make_float2(fmaxf(acc[mt][nt][0], 0.f),
                                       fmaxf(acc[mt][nt][1], 0.f));
                *(float2*)(out + (size_t)r0 * DD + c) = v;
            }
            if (r0 + 8 < M) {
                float2 v = make_float2(fmaxf(acc[mt][nt][2], 0.f),
                                       fmaxf(acc[mt][nt][3], 0.f));
                *(float2*)(out + (size_t)(r0 + 8) * DD + c) = v;
            }
        }
    }
}

// ---------------- tail: re-zero counters/flags/barriers for next replay ----------------
__global__ void tail_kernel() {
    int i = blockIdx.x * blockDim.x + threadIdx.x;
    if (i < NN0) g_fill0[i] = 0;
    else if (i < NN0 + NN2) g_fill2[i - NN0] = 0;
    else if (i < NN0 + NN2 + NBT) g_flagA[i - NN0 - NN2] = 0;
    else if (i == NN0 + NN2 + NBT)     g_bar1 = 0;
    else if (i == NN0 + NN2 + NBT + 1) g_bar2 = 0;
}

// ---------------- host launch ----------------
extern "C" void kernel_launch(void* const* d_in, const int* in_sizes, int n_in,
                              void* d_out, int out_size) {
    const float* x0  = (const float*)d_in[0];
    const float* x1  = (const float*)d_in[1];
    const int*   r00 = (const int*)  d_in[2];
    const int*   c00 = (const int*)  d_in[3];
    const float* v00 = (const float*)d_in[4];
    const int*   r12 = (const int*)  d_in[5];
    const int*   c12 = (const int*)  d_in[6];
    const float* v12 = (const float*)d_in[7];
    const float* W0  = (const float*)d_in[8];
    const float* W12 = (const float*)d_in[9];

    float* out    = (float*)d_out;
    float* out_y0 = out;
    float* out_x1 = out + (size_t)NN0 * DD;
    float* out_y2 = out + (size_t)(NN0 + NN1) * DD;

    front_kernel<<<NBT, 1024>>>(x0, x1, r00, r12, out_x1);                 // #1
    fill2_kernel<<<(NNZ00 + NNZ12 + 255) / 256, 256>>>(r00, c00, v00,
                                                       r12, c12, v12);    // #2
    spmm2_kernel<<<((NN0 + NN2) * 32 + 255) / 256, 256>>>();               // #3
    cudaFuncSetAttribute(gemm2_tf32_relu_kernel,
                         cudaFuncAttributeMaxDynamicSharedMemorySize, GSMEM);
    gemm2_tf32_relu_kernel<<<NBLK0 + NBLK2, 256, GSMEM>>>(W0, W12,
                                                          out_y0, out_y2); // #4 (profiled)
    tail_kernel<<<(NN0 + NN2 + NBT + 2 + 255) / 256, 256>>>();             // #5
}

// round 7
// speedup vs baseline: 2.2369x; 1.1227x over previous
#include <cuda_runtime.h>
#include <cuda_fp16.h>
#include <math.h>
#include <stdint.h>

#define NN0 100000
#define NN1 150000
#define NN2 50000
#define NNZ00 1600000
#define NNZ12 200000
#define DD 128

#define NB0 98              // ceil(NN0/1024)
#define NB2 49              // ceil(NN2/1024)
#define NBT (NB0 + NB2)     // 147 <= 148 SMs: all blocks co-resident at occ 1
#define NAT (NBT * 1024)

// ---------------- device scratch (zero-initialized; tail restores zeros) ----------------
__device__ uint2 g_h0[(size_t)NN0 * 32];       // relu(x0) fp16
__device__ uint2 g_h1[(size_t)NN1 * 32];       // relu(x1) fp16
__device__ uint2 g_S0h[(size_t)NN0 * 32];      // S0 fp16
__device__ uint2 g_S2h[(size_t)NN2 * 32];      // S2 fp16
__device__ __half g_WT0hi[DD * DD];            // W0^T split planes [n][k]
__device__ __half g_WT0lo[DD * DD];
__device__ __half g_WT2hi[DD * DD];            // W12^T split planes
__device__ __half g_WT2lo[DD * DD];
__device__ __align__(16) int g_rp0[NN0 + 4];
__device__ __align__(16) int g_fill0[NN0];
__device__ __align__(16) int g_rp2[NN2 + 4];
__device__ __align__(16) int g_fill2[NN2];
__device__ int  g_flagA[NBT];
__device__ int  g_bar1, g_bar2;
__device__ int2 g_e0[NNZ00];
__device__ int2 g_e2[NNZ12];

// ---------------- fused front: hist + conversions + W split + out_x1 + scan ----------------
__device__ __forceinline__ void grid_barrier(int* ctr) {
    __syncthreads();
    if (threadIdx.x == 0) {
        atomicAdd(ctr, 1);
        while (*(volatile int*)ctr < NBT) __nanosleep(40);
    }
    __syncthreads();
}

__global__ __launch_bounds__(1024, 1)
void front_kernel(const float* __restrict__ x0, const float* __restrict__ x1,
                  const int* __restrict__ r00, const int* __restrict__ r12,
                  const float* __restrict__ W0, const float* __restrict__ W12,
                  float* __restrict__ out_x1) {
    int tid  = threadIdx.x;
    int gtid = blockIdx.x * 1024 + tid;

    // histogram both edge sets
    for (int i = gtid; i < NNZ00; i += NAT) atomicAdd(&g_fill0[r00[i]], 1);
    for (int i = gtid; i < NNZ12; i += NAT) atomicAdd(&g_fill2[r12[i]], 1);

    // W transpose + fp16 split (tiny)
    for (int i = gtid; i < DD * DD; i += NAT) {
        int r = i >> 7, c = i & 127;
        float w = W0[i];
        __half h = __float2half_rn(w);
        g_WT0hi[c * DD + r] = h;
        g_WT0lo[c * DD + r] = __float2half_rn(w - __half2float(h));
        w = W12[i];
        h = __float2half_rn(w);
        g_WT2hi[c * DD + r] = h;
        g_WT2lo[c * DD + r] = __float2half_rn(w - __half2float(h));
    }

    // relu + fp16 conversion of x0, x1 (+ fp32 relu(x1) straight to d_out)
    for (int i = gtid; i < NN0 * 32; i += NAT) {
        float4 v = ((const float4*)x0)[i];
        half2 p0 = __floats2half2_rn(fmaxf(v.x, 0.f), fmaxf(v.y, 0.f));
        half2 p1 = __floats2half2_rn(fmaxf(v.z, 0.f), fmaxf(v.w, 0.f));
        g_h0[i] = make_uint2(*(uint32_t*)&p0, *(uint32_t*)&p1);
    }
    for (int i = gtid; i < NN1 * 32; i += NAT) {
        float4 v = ((const float4*)x1)[i];
        v.x = fmaxf(v.x, 0.f); v.y = fmaxf(v.y, 0.f);
        v.z = fmaxf(v.z, 0.f); v.w = fmaxf(v.w, 0.f);
        ((float4*)out_x1)[i] = v;
        half2 p0 = __floats2half2_rn(v.x, v.y);
        half2 p1 = __floats2half2_rn(v.z, v.w);
        g_h1[i] = make_uint2(*(uint32_t*)&p0, *(uint32_t*)&p1);
    }

    grid_barrier(&g_bar1);

    // per-chunk scan
    __shared__ int wsum[32];
    __shared__ int s_off;
    int b = blockIdx.x;
    int* cntfill; int* rp; int R; int base0; int lastcb;
    if (b < NB0) { cntfill = g_fill0; rp = g_rp0; R = NN0; base0 = 0;   lastcb = NB0 - 1; }
    else         { cntfill = g_fill2; rp = g_rp2; R = NN2; base0 = NB0; lastcb = NB2 - 1; }
    int cb  = b - base0;
    int idx = cb * 1024 + tid;
    int c = (idx < R) ? cntfill[idx] : 0;

    int lane = tid & 31, w = tid >> 5;
    int inc = c;
    #pragma unroll
    for (int off = 1; off < 32; off <<= 1) {
        int v = __shfl_up_sync(0xffffffffu, inc, off);
        if (lane >= off) inc += v;
    }
    if (lane == 31) wsum[w] = inc;
    if (tid == 0) s_off = 0;
    __syncthreads();
    if (w == 0) {
        int v = wsum[lane];
        int winc = v;
        #pragma unroll
        for (int off = 1; off < 32; off <<= 1) {
            int u = __shfl_up_sync(0xffffffffu, winc, off);
            if (lane >= off) winc += u;
        }
        wsum[lane] = winc - v;
        if (lane == 31) g_flagA[b] = winc;
    }

    grid_barrier(&g_bar2);

    int local = 0;
    for (int j = base0 + tid; j < b; j += 1024) local += g_flagA[j];
    if (local) atomicAdd(&s_off, local);
    __syncthreads();
    int off = s_off;

    if (idx < R) {
        int v = off + wsum[w] + inc - c;
        rp[idx]      = v;
        cntfill[idx] = v;
    }
    if (tid == 1023 && cb == lastcb) rp[R] = off + wsum[31] + inc;
}

// ---------------- CSR fill ----------------
__global__ void fill2_kernel(const int* __restrict__ r00, const int* __restrict__ c00,
                             const float* __restrict__ v00,
                             const int* __restrict__ r12, const int* __restrict__ c12,
                             const float* __restrict__ v12) {
    int i = blockIdx.x * blockDim.x + threadIdx.x;
    if (i < NNZ00) {
        int p = atomicAdd(&g_fill0[r00[i]], 1);
        g_e0[p] = make_int2(c00[i], __float_as_int(v00[i]));
    } else {
        int j = i - NNZ00;
        if (j < NNZ12) {
            int p = atomicAdd(&g_fill2[r12[j]], 1);
            g_e2[p] = make_int2(c12[j], __float_as_int(v12[j]));
        }
    }
}

// ---------------- SpMM: warp-per-row, fp16 gather, fp32 accum, fp16 store ----------------
__device__ __forceinline__ float4 h4f(uint2 q) {
    float2 f0 = __half22float2(*(half2*)&q.x);
    float2 f1 = __half22float2(*(half2*)&q.y);
    return make_float4(f0.x, f0.y, f1.x, f1.y);
}

__device__ __forceinline__ void spmm_row(const uint2* __restrict__ xh,
                                         const int* __restrict__ rp,
                                         const int2* __restrict__ ed,
                                         uint2* __restrict__ S, int row, int lane) {
    int s = rp[row], e = rp[row + 1];
    float4 acc = make_float4(0.f, 0.f, 0.f, 0.f);
    int i = s;
    for (; i + 4 <= e; i += 4) {
        int2 e0 = ed[i], e1 = ed[i + 1], e2 = ed[i + 2], e3 = ed[i + 3];
        float4 xa = h4f(xh[(size_t)e0.x * 32 + lane]);
        float4 xb = h4f(xh[(size_t)e1.x * 32 + lane]);
        float4 xc = h4f(xh[(size_t)e2.x * 32 + lane]);
        float4 xd = h4f(xh[(size_t)e3.x * 32 + lane]);
        float v0 = __int_as_float(e0.y), v1 = __int_as_float(e1.y);
        float v2 = __int_as_float(e2.y), v3 = __int_as_float(e3.y);
        acc.x += v0 * xa.x + v1 * xb.x + v2 * xc.x + v3 * xd.x;
        acc.y += v0 * xa.y + v1 * xb.y + v2 * xc.y + v3 * xd.y;
        acc.z += v0 * xa.z + v1 * xb.z + v2 * xc.z + v3 * xd.z;
        acc.w += v0 * xa.w + v1 * xb.w + v2 * xc.w + v3 * xd.w;
    }
    for (; i < e; i++) {
        int2 e0 = ed[i];
        float v0 = __int_as_float(e0.y);
        float4 xa = h4f(xh[(size_t)e0.x * 32 + lane]);
        acc.x += v0 * xa.x; acc.y += v0 * xa.y;
        acc.z += v0 * xa.z; acc.w += v0 * xa.w;
    }
    half2 p0 = __floats2half2_rn(acc.x, acc.y);
    half2 p1 = __floats2half2_rn(acc.z, acc.w);
    S[(size_t)row * 32 + lane] = make_uint2(*(uint32_t*)&p0, *(uint32_t*)&p1);
}

__global__ void spmm2_kernel() {
    int warp = (blockIdx.x * blockDim.x + threadIdx.x) >> 5;
    int lane = threadIdx.x & 31;
    if (warp < NN0)            spmm_row(g_h0, g_rp0, g_e0, g_S0h, warp, lane);
    else if (warp < NN0 + NN2) spmm_row(g_h1, g_rp2, g_e2, g_S2h, warp - NN0, lane);
}

// ---------------- GEMM: fp16 m16n8k16 HMMA, split-W (2 mma), fp32 accum, relu fused ----------------
// A tile 64x128 fp16, W^T planes 128x128 fp16. Pad rows to 136 halves (68 words):
// fragment bank = (4g + i) mod 32 -> bijective over warp, conflict-free.
#define PADH 136
#define SW_WORDS (DD * PADH / 2)               // per plane, in uint32
#define GSMEM ((2 * DD * PADH + 64 * PADH) * 2)  // bytes: 2 W planes + A, all fp16
#define NBLK0 ((NN0 + 63) / 64)
#define NBLK2 ((NN2 + 63) / 64)

__device__ __forceinline__ void mma_f16(float* d, const uint32_t* a, const uint32_t* b) {
    asm volatile(
        "mma.sync.aligned.m16n8k16.row.col.f32.f16.f16.f32 "
        "{%0,%1,%2,%3}, {%4,%5,%6,%7}, {%8,%9}, {%0,%1,%2,%3};\n"
        : "+f"(d[0]), "+f"(d[1]), "+f"(d[2]), "+f"(d[3])
        : "r"(a[0]), "r"(a[1]), "r"(a[2]), "r"(a[3]), "r"(b[0]), "r"(b[1]));
}

__global__ __launch_bounds__(256, 2)
void gemm2_f16_relu_kernel(float* __restrict__ out_y0, float* __restrict__ out_y2) {
    const uint2* Sh; const __half* WThi; const __half* WTlo; float* out; int M, bid;
    if (blockIdx.x < NBLK0) {
        Sh = g_S0h; WThi = g_WT0hi; WTlo = g_WT0lo; out = out_y0; M = NN0; bid = blockIdx.x;
    } else {
        Sh = g_S2h; WThi = g_WT2hi; WTlo = g_WT2lo; out = out_y2; M = NN2; bid = blockIdx.x - NBLK0;
    }

    extern __shared__ __half hsm[];
    __half* sWhi = hsm;                 // [128][PADH]
    __half* sWlo = hsm + DD * PADH;     // [128][PADH]
    __half* sA   = hsm + 2 * DD * PADH; // [64][PADH]
    int tid = threadIdx.x;
    int m0 = bid * 64;

    // stage W planes (coalesced int4 = 8 halves)
    for (int idx = tid; idx < DD * 16; idx += 256) {
        int n = idx >> 4, kc = idx & 15;
        *(int4*)(sWhi + n * PADH + kc * 8) = ((const int4*)WThi)[idx];
        *(int4*)(sWlo + n * PADH + kc * 8) = ((const int4*)WTlo)[idx];
    }
    // stage A rows (fp16 direct)
    for (int idx = tid; idx < 64 * 32; idx += 256) {
        int r = idx >> 5, q = idx & 31;
        int gr = m0 + r;
        uint2 v = make_uint2(0u, 0u);
        if (gr < M) v = Sh[(size_t)gr * 32 + q];
        *(uint2*)(sA + r * PADH + q * 4) = v;
    }
    __syncthreads();

    int lane = tid & 31, wid = tid >> 5;
    int g = lane >> 2, i = lane & 3;
    int mg = wid & 1, ng = wid >> 1;     // 2 x 4 warp grid: warp = 32 rows x 32 cols

    const uint32_t* sA32 = (const uint32_t*)sA;
    const uint32_t* sH32 = (const uint32_t*)sWhi;
    const uint32_t* sL32 = (const uint32_t*)sWlo;

    float acc[2][4][4];
    #pragma unroll
    for (int mt = 0; mt < 2; mt++)
        #pragma unroll
        for (int nt = 0; nt < 4; nt++)
            #pragma unroll
            for (int q = 0; q < 4; q++) acc[mt][nt][q] = 0.f;

    #pragma unroll
    for (int kk = 0; kk < 8; kk++) {     // k = 16 per step
        int kw = kk * 8 + i;             // word (half2) column
        uint32_t a[2][4], bh[4][2], bl[4][2];
        #pragma unroll
        for (int mt = 0; mt < 2; mt++) {
            int row = (mg * 32 + mt * 16 + g) * (PADH / 2);
            a[mt][0] = sA32[row + kw];
            a[mt][1] = sA32[row + 8 * (PADH / 2) + kw];
            a[mt][2] = sA32[row + kw + 4];
            a[mt][3] = sA32[row + 8 * (PADH / 2) + kw + 4];
        }
        #pragma unroll
        for (int nt = 0; nt < 4; nt++) {
            int n = (ng * 32 + nt * 8 + g) * (PADH / 2);
            bh[nt][0] = sH32[n + kw];
            bh[nt][1] = sH32[n + kw + 4];
            bl[nt][0] = sL32[n + kw];
            bl[nt][1] = sL32[n + kw + 4];
        }
        #pragma unroll
        for (int mt = 0; mt < 2; mt++)
            #pragma unroll
            for (int nt = 0; nt < 4; nt++) {
                mma_f16(acc[mt][nt], a[mt], bl[nt]);   // small term first
                mma_f16(acc[mt][nt], a[mt], bh[nt]);
            }
    }

    #pragma unroll
    for (int mt = 0; mt < 2; mt++) {
        int r0 = m0 + mg * 32 + mt * 16 + g;
        #pragma unroll
        for (int nt = 0; nt < 4; nt++) {
            int c = ng * 32 + nt * 8 + i * 2;
            if (r0 < M) {
                float2 v = make_float2(fmaxf(acc[mt][nt][0], 0.f),
                                       fmaxf(acc[mt][nt][1], 0.f));
                *(float2*)(out + (size_t)r0 * DD + c) = v;
            }
            if (r0 + 8 < M) {
                float2 v = make_float2(fmaxf(acc[mt][nt][2], 0.f),
                                       fmaxf(acc[mt][nt][3], 0.f));
                *(float2*)(out + (size_t)(r0 + 8) * DD + c) = v;
            }
        }
    }
}

// ---------------- tail: re-zero counters/flags/barriers for next replay ----------------
__global__ void tail_kernel() {
    int i = blockIdx.x * blockDim.x + threadIdx.x;
    if (i < NN0) g_fill0[i] = 0;
    else if (i < NN0 + NN2) g_fill2[i - NN0] = 0;
    else if (i < NN0 + NN2 + NBT) g_flagA[i - NN0 - NN2] = 0;
    else if (i == NN0 + NN2 + NBT)     g_bar1 = 0;
    else if (i == NN0 + NN2 + NBT + 1) g_bar2 = 0;
}

// ---------------- host launch ----------------
extern "C" void kernel_launch(void* const* d_in, const int* in_sizes, int n_in,
                              void* d_out, int out_size) {
    const float* x0  = (const float*)d_in[0];
    const float* x1  = (const float*)d_in[1];
    const int*   r00 = (const int*)  d_in[2];
    const int*   c00 = (const int*)  d_in[3];
    const float* v00 = (const float*)d_in[4];
    const int*   r12 = (const int*)  d_in[5];
    const int*   c12 = (const int*)  d_in[6];
    const float* v12 = (const float*)d_in[7];
    const float* W0  = (const float*)d_in[8];
    const float* W12 = (const float*)d_in[9];

    float* out    = (float*)d_out;
    float* out_y0 = out;
    float* out_x1 = out + (size_t)NN0 * DD;
    float* out_y2 = out + (size_t)(NN0 + NN1) * DD;

    front_kernel<<<NBT, 1024>>>(x0, x1, r00, r12, W0, W12, out_x1);        // #1
    fill2_kernel<<<(NNZ00 + NNZ12 + 255) / 256, 256>>>(r00, c00, v00,
                                                       r12, c12, v12);    // #2
    spmm2_kernel<<<((NN0 + NN2) * 32 + 255) / 256, 256>>>();               // #3
    cudaFuncSetAttribute(gemm2_f16_relu_kernel,
                         cudaFuncAttributeMaxDynamicSharedMemorySize, GSMEM);
    gemm2_f16_relu_kernel<<<NBLK0 + NBLK2, 256, GSMEM>>>(out_y0, out_y2);  // #4 (profiled)
    tail_kernel<<<(NN0 + NN2 + NBT + 2 + 255) / 256, 256>>>();             // #5
}